// round 5
// baseline (speedup 1.0000x reference)
#include <cuda_runtime.h>
#include <cuda_bf16.h>
#include <cstdint>

// Problem constants (B=32, C=1 heat, H=W=256, K=500)
#define NB     32
#define WID    256
#define HW     65536
#define KTOP   500
#define NIMG   64          // 32 pred images (NMS'd) + 32 gt images (raw)
#define CAND_MAX 8192      // max stored NMS candidates per pred image (~7.3k expected)
#define SURV   1024        // survivors after value-bin prune (E~516, 20-sigma margin)
#define BINS   4096        // value-based bins: bin = clamp((int)(v*4096), 0, 4095)

// Scratch (static device globals — zero-initialized; every consumer resets what
// it consumed so graph replays see the same initial state)
__device__ unsigned long long g_cand[NB][CAND_MAX];   // 2 MB (pred only)
__device__ int      g_cnt[NB];
__device__ float    g_xs[NIMG][KTOP];
__device__ float    g_ys[NIMG][KTOP];
__device__ double   g_sum;
__device__ int      g_tot;
__device__ unsigned g_ticket;

__device__ __forceinline__ int val_bin(float v) {
    int b = (int)(v * 4096.0f);
    if (b < 0) b = 0;
    if (b > BINS - 1) b = BINS - 1;
    return b;   // monotone non-decreasing in v
}

// ---------------------------------------------------------------------------
// 3x3 NMS on PRED heatmaps only (reference NMS-es pred_hm, not gt_hm).
// One block per row: 3 rows staged in smem (3 LDG/pixel instead of 9).
// Survivor key: (~float_bits << 32) | linear_index  => ascending 64-bit sort
// reproduces lax.top_k ordering (value desc, index asc).
// Candidate slots reserved with warp-aggregated atomics (1 ATOMG per warp).
__global__ void k_nms(const float* __restrict__ pred_hm) {
    __shared__ float r[3][WID];
    int img = blockIdx.y;
    int y = blockIdx.x;
    int x = threadIdx.x;
    const float* hm = pred_hm + (size_t)img * HW;

    float up  = (y > 0)       ? __ldg(&hm[(y - 1) * WID + x]) : -1.0f;
    float mid =                 __ldg(&hm[y * WID + x]);
    float dn  = (y < WID - 1) ? __ldg(&hm[(y + 1) * WID + x]) : -1.0f;
    r[0][x] = up; r[1][x] = mid; r[2][x] = dn;
    __syncthreads();

    float v = mid;
    bool ok = (v > 0.0f);
    if (ok) {
        if (up > v || dn > v) ok = false;
        if (ok && x > 0) {
            if (r[0][x-1] > v || r[1][x-1] > v || r[2][x-1] > v) ok = false;
        }
        if (ok && x < WID - 1) {
            if (r[0][x+1] > v || r[1][x+1] > v || r[2][x+1] > v) ok = false;
        }
    }

    unsigned ballot = __ballot_sync(0xffffffffu, ok);
    if (ok) {
        int lane = threadIdx.x & 31;
        int leader = __ffs(ballot) - 1;
        int base = 0;
        if (lane == leader) base = atomicAdd(&g_cnt[img], __popc(ballot));
        base = __shfl_sync(ballot, base, leader);
        int slot = base + __popc(ballot & ((1u << lane) - 1u));
        if (slot < CAND_MAX) {
            unsigned fb = __float_as_uint(v);   // v > 0 => monotone bits
            g_cand[img][slot] =
                ((unsigned long long)(~fb) << 32) | (unsigned)(y * WID + x);
        }
    }
}

// ---------------------------------------------------------------------------
// Per-image exact ordered top-500.
//   img <  NB : candidates = NMS survivors (g_cand)
//   img >= NB : candidates = ALL raw pixels of gt_hm (reference has no gt NMS)
// 1) 4096 value-bins histogram  2) suffix-scan -> bin of rank 500
// 3) collect survivors (E~516)  4) bitonic sort 1024 keys -> ranks 0..499
__global__ void __launch_bounds__(1024) k_select(const float* __restrict__ gt_hm) {
    __shared__ int hist[BINS];                 // 16 KB
    __shared__ unsigned long long keys[SURV];  // 8 KB
    __shared__ int psum[1024];                 // 4 KB
    __shared__ int s_bstar;
    __shared__ int s_nsurv;

    int img = blockIdx.x;
    int tid = threadIdx.x;
    bool is_gt = (img >= NB);
    const float* hm = is_gt ? (gt_hm + (size_t)(img - NB) * HW) : nullptr;
    int n;
    if (is_gt) n = HW;
    else { n = g_cnt[img]; if (n > CAND_MAX) n = CAND_MAX; }

    for (int i = tid; i < BINS; i += 1024) hist[i] = 0;
    if (tid == 0) { s_bstar = 0; s_nsurv = 0; }
    __syncthreads();

    for (int i = tid; i < n; i += 1024) {
        float v = is_gt ? __ldg(&hm[i])
                        : __uint_as_float(~(unsigned)(g_cand[img][i] >> 32));
        atomicAdd(&hist[val_bin(v)], 1);
    }
    __syncthreads();

    // group sums of 4 bins each, then Hillis-Steele inclusive suffix scan
    psum[tid] = hist[4*tid] + hist[4*tid+1] + hist[4*tid+2] + hist[4*tid+3];
    __syncthreads();
    for (int off = 1; off < 1024; off <<= 1) {
        int vv = psum[tid];
        if (tid + off < 1024) vv += psum[tid + off];
        __syncthreads();
        psum[tid] = vv;
        __syncthreads();
    }
    // unique boundary group: suffix(t) >= K but suffix(t+1) < K
    int above = (tid < 1023) ? psum[tid + 1] : 0;
    if (psum[tid] >= KTOP && above < KTOP) {
        int c = above;
        int bstar = 4 * tid;
        for (int b = 4 * tid + 3; b >= 4 * tid; --b) {
            c += hist[b];
            if (c >= KTOP) { bstar = b; break; }
        }
        s_bstar = bstar;
    }
    __syncthreads();

    int bstar = s_bstar;
    for (int i = tid; i < n; i += 1024) {
        unsigned fb; unsigned idx;
        if (is_gt) { fb = __float_as_uint(__ldg(&hm[i])); idx = (unsigned)i; }
        else {
            unsigned long long key = g_cand[img][i];
            fb = ~(unsigned)(key >> 32);
            idx = (unsigned)(key & 0xFFFFFFFFULL);
        }
        if (val_bin(__uint_as_float(fb)) >= bstar) {
            int slot = atomicAdd(&s_nsurv, 1);
            if (slot < SURV)
                keys[slot] = ((unsigned long long)(~fb) << 32) | idx;
        }
    }
    __syncthreads();
    int ns = s_nsurv; if (ns > SURV) ns = SURV;
    if (tid >= ns) keys[tid] = 0xFFFFFFFFFFFFFFFFULL;
    __syncthreads();

    // bitonic sort ascending over 1024 keys (asc key == value desc, idx asc)
    for (unsigned kk = 2; kk <= SURV; kk <<= 1) {
        for (unsigned j = kk >> 1; j > 0; j >>= 1) {
            unsigned i = tid;
            unsigned ixj = i ^ j;
            if (ixj > i) {
                unsigned long long a = keys[i], b = keys[ixj];
                bool upd = ((i & kk) == 0);
                if ((a > b) == upd) { keys[i] = b; keys[ixj] = a; }
            }
            __syncthreads();
        }
    }

    if (tid < KTOP) {
        unsigned p = (unsigned)(keys[tid] & 0xFFFFFFFFULL);
        g_xs[img][tid] = (float)(p & (WID - 1));
        g_ys[img][tid] = (float)(p >> 8);
    }
    // reset consumed counter for the next graph replay
    if (!is_gt && tid == 0) g_cnt[img] = 0;
}

// ---------------------------------------------------------------------------
__device__ __forceinline__ void assemble(float* o, float xs, float ys,
                                         const float* wh, bool m) {
    // m is exactly 0/1 in the reference, so branching is bit-exact with blend
    o[0] = xs; o[1] = ys;
    if (m) {
        o[2] = xs + wh[0]; o[3] = ys + wh[1];
        o[4] = xs + wh[2]; o[5] = ys + wh[3];
        o[6] = xs + wh[4]; o[7] = ys + wh[5];
        o[8] = xs + wh[6]; o[9] = ys + wh[7];
    } else {
        o[2] = xs;                 o[3] = ys - wh[9] * 0.5f;
        o[4] = xs + wh[8] * 0.5f;  o[5] = ys;
        o[6] = xs;                 o[7] = ys + wh[9] * 0.5f;
        o[8] = xs - wh[8] * 0.5f;  o[9] = ys;
    }
}

#define LOSS_TPB 128
__global__ void k_loss(const float* __restrict__ pred_wh, const float* __restrict__ pred_reg,
                       const float* __restrict__ pred_cls,
                       const float* __restrict__ gt_wh, const float* __restrict__ gt_reg,
                       const float* __restrict__ gt_cls,
                       const int* __restrict__ gt_ind, const int* __restrict__ gt_mask,
                       float* __restrict__ out) {
    int t = blockIdx.x * LOSS_TPB + threadIdx.x;
    float lsum = 0.f;
    int lcnt = 0;
    if (t < NB * KTOP) {
        int b = t / KTOP;
        int k = t - b * KTOP;
        if (gt_mask[t] != 0) {
            lcnt = 10;
            int ind = gt_ind[t];
            float xs  = g_xs[b][k] + __ldg(&pred_reg[(size_t)(b * 2) * HW + ind]);
            float ys  = g_ys[b][k] + __ldg(&pred_reg[(size_t)(b * 2 + 1) * HW + ind]);
            float gxs = g_xs[NB + b][k] + __ldg(&gt_reg[2 * t]);
            float gys = g_ys[NB + b][k] + __ldg(&gt_reg[2 * t + 1]);
            float wh[10], gwh[10];
            #pragma unroll
            for (int c = 0; c < 10; c++)
                wh[c] = __ldg(&pred_wh[((size_t)b * 10 + c) * HW + ind]);
            #pragma unroll
            for (int c = 0; c < 10; c++)
                gwh[c] = __ldg(&gt_wh[10 * t + c]);
            bool m  = __ldg(&pred_cls[(size_t)b * HW + ind]) > 0.8f;
            bool gm = __ldg(&gt_cls[t]) > 0.8f;
            float pp[10], tt[10];
            assemble(pp, xs, ys, wh, m);
            assemble(tt, gxs, gys, gwh, gm);
            #pragma unroll
            for (int c = 0; c < 10; c++) {
                float d = fabsf(pp[c] - tt[c]);
                lsum += (d < 1.f) ? 0.5f * d * d : (d - 0.5f);
            }
        }
    }
    // block reduce
    #pragma unroll
    for (int off = 16; off > 0; off >>= 1) {
        lsum += __shfl_down_sync(0xffffffffu, lsum, off);
        lcnt += __shfl_down_sync(0xffffffffu, lcnt, off);
    }
    __shared__ float wsum[LOSS_TPB / 32];
    __shared__ int   wcnt[LOSS_TPB / 32];
    int warp = threadIdx.x >> 5, lane = threadIdx.x & 31;
    if (lane == 0) { wsum[warp] = lsum; wcnt[warp] = lcnt; }
    __syncthreads();
    if (threadIdx.x == 0) {
        float s = 0.f; int c = 0;
        #pragma unroll
        for (int w = 0; w < LOSS_TPB / 32; w++) { s += wsum[w]; c += wcnt[w]; }
        atomicAdd(&g_sum, (double)s);
        atomicAdd(&g_tot, c);
        __threadfence();
        unsigned ticket = atomicAdd(&g_ticket, 1u);
        if (ticket == gridDim.x - 1) {   // last block: finalize + reset state
            double fs = g_sum;
            int tot = g_tot;
            float loss = 0.f;
            if (tot > 0) loss = (float)(fs / (double)(tot < 1 ? 1 : tot));
            out[0] = loss;
            g_sum = 0.0; g_tot = 0; g_ticket = 0u;
        }
    }
}

// ---------------------------------------------------------------------------
extern "C" void kernel_launch(void* const* d_in, const int* in_sizes, int n_in,
                              void* d_out, int out_size) {
    const float* pred_hm  = (const float*)d_in[0];
    const float* pred_wh  = (const float*)d_in[1];
    const float* pred_reg = (const float*)d_in[2];
    const float* pred_cls = (const float*)d_in[3];
    const float* gt_hm    = (const float*)d_in[4];
    const float* gt_wh    = (const float*)d_in[5];
    const float* gt_reg   = (const float*)d_in[6];
    const float* gt_cls   = (const float*)d_in[7];
    const int*   gt_ind   = (const int*)d_in[8];
    const int*   gt_mask  = (const int*)d_in[9];
    float* out = (float*)d_out;

    k_nms<<<dim3(WID, NB), WID>>>(pred_hm);
    k_select<<<NIMG, 1024>>>(gt_hm);
    k_loss<<<(NB * KTOP + LOSS_TPB - 1) / LOSS_TPB, LOSS_TPB>>>(
        pred_wh, pred_reg, pred_cls, gt_wh, gt_reg, gt_cls, gt_ind, gt_mask, out);
}

// round 6
// speedup vs baseline: 1.0034x; 1.0034x over previous
#include <cuda_runtime.h>
#include <cuda_bf16.h>
#include <cstdint>

// Problem constants (B=32, C=1 heat, H=W=256, K=500)
#define NB     32
#define WID    256
#define HW     65536
#define KTOP   500
#define NIMG   64          // 32 pred images (NMS'd) + 32 gt images (raw)
#define CAND_MAX 8192      // max stored NMS candidates per pred image (~7.3k expected)
#define SURV   1024        // survivors after value-bin prune (E~516, 20-sigma margin)
#define BINS   4096        // value-based bins: bin = clamp((int)(v*4096), 0, 4095)

// Scratch (static device globals — zero-initialized; every consumer resets what
// it consumed so graph replays see the same initial state)
__device__ unsigned long long g_cand[NB][CAND_MAX];   // 2 MB (pred only)
__device__ int      g_cnt[NB];
__device__ float    g_xs[NIMG][KTOP];
__device__ float    g_ys[NIMG][KTOP];
__device__ double   g_sum;
__device__ int      g_tot;
__device__ unsigned g_ticket;

__device__ __forceinline__ int val_bin(float v) {
    int b = (int)(v * 4096.0f);
    if (b < 0) b = 0;
    if (b > BINS - 1) b = BINS - 1;
    return b;   // monotone non-decreasing in v
}

// ---------------------------------------------------------------------------
// 3x3 NMS on PRED heatmaps only (reference NMS-es pred_hm, not gt_hm).
// One block per row: 3 rows staged in smem (3 LDG/pixel instead of 9).
// Survivor key: (~float_bits << 32) | linear_index  => ascending 64-bit sort
// reproduces lax.top_k ordering (value desc, index asc).
// Candidate slots reserved with warp-aggregated atomics (1 ATOMG per warp).
__global__ void k_nms(const float* __restrict__ pred_hm) {
    __shared__ float r[3][WID];
    int img = blockIdx.y;
    int y = blockIdx.x;
    int x = threadIdx.x;
    const float* hm = pred_hm + (size_t)img * HW;

    float up  = (y > 0)       ? __ldg(&hm[(y - 1) * WID + x]) : -1.0f;
    float mid =                 __ldg(&hm[y * WID + x]);
    float dn  = (y < WID - 1) ? __ldg(&hm[(y + 1) * WID + x]) : -1.0f;
    r[0][x] = up; r[1][x] = mid; r[2][x] = dn;
    __syncthreads();

    float v = mid;
    bool ok = (v > 0.0f);
    if (ok) {
        if (up > v || dn > v) ok = false;
        if (ok && x > 0) {
            if (r[0][x-1] > v || r[1][x-1] > v || r[2][x-1] > v) ok = false;
        }
        if (ok && x < WID - 1) {
            if (r[0][x+1] > v || r[1][x+1] > v || r[2][x+1] > v) ok = false;
        }
    }

    unsigned ballot = __ballot_sync(0xffffffffu, ok);
    if (ok) {
        int lane = threadIdx.x & 31;
        int leader = __ffs(ballot) - 1;
        int base = 0;
        if (lane == leader) base = atomicAdd(&g_cnt[img], __popc(ballot));
        base = __shfl_sync(ballot, base, leader);
        int slot = base + __popc(ballot & ((1u << lane) - 1u));
        if (slot < CAND_MAX) {
            unsigned fb = __float_as_uint(v);   // v > 0 => monotone bits
            g_cand[img][slot] =
                ((unsigned long long)(~fb) << 32) | (unsigned)(y * WID + x);
        }
    }
}

// ---------------------------------------------------------------------------
// Per-image exact ordered top-500.
//   img <  NB : candidates = NMS survivors (g_cand)
//   img >= NB : candidates = ALL raw pixels of gt_hm (reference has no gt NMS)
// 1) 4096 value-bins histogram  2) suffix-scan -> bin of rank 500
// 3) collect survivors (E~516)  4) bitonic sort 1024 keys -> ranks 0..499
__global__ void __launch_bounds__(1024) k_select(const float* __restrict__ gt_hm) {
    __shared__ int hist[BINS];                 // 16 KB
    __shared__ unsigned long long keys[SURV];  // 8 KB
    __shared__ int psum[1024];                 // 4 KB
    __shared__ int s_bstar;
    __shared__ int s_nsurv;

    int img = blockIdx.x;
    int tid = threadIdx.x;
    bool is_gt = (img >= NB);
    const float* hm = is_gt ? (gt_hm + (size_t)(img - NB) * HW) : nullptr;
    int n;
    if (is_gt) n = HW;
    else { n = g_cnt[img]; if (n > CAND_MAX) n = CAND_MAX; }

    for (int i = tid; i < BINS; i += 1024) hist[i] = 0;
    if (tid == 0) { s_bstar = 0; s_nsurv = 0; }
    __syncthreads();

    for (int i = tid; i < n; i += 1024) {
        float v = is_gt ? __ldg(&hm[i])
                        : __uint_as_float(~(unsigned)(g_cand[img][i] >> 32));
        atomicAdd(&hist[val_bin(v)], 1);
    }
    __syncthreads();

    // group sums of 4 bins each, then Hillis-Steele inclusive suffix scan
    psum[tid] = hist[4*tid] + hist[4*tid+1] + hist[4*tid+2] + hist[4*tid+3];
    __syncthreads();
    for (int off = 1; off < 1024; off <<= 1) {
        int vv = psum[tid];
        if (tid + off < 1024) vv += psum[tid + off];
        __syncthreads();
        psum[tid] = vv;
        __syncthreads();
    }
    // unique boundary group: suffix(t) >= K but suffix(t+1) < K
    int above = (tid < 1023) ? psum[tid + 1] : 0;
    if (psum[tid] >= KTOP && above < KTOP) {
        int c = above;
        int bstar = 4 * tid;
        for (int b = 4 * tid + 3; b >= 4 * tid; --b) {
            c += hist[b];
            if (c >= KTOP) { bstar = b; break; }
        }
        s_bstar = bstar;
    }
    __syncthreads();

    int bstar = s_bstar;
    for (int i = tid; i < n; i += 1024) {
        unsigned fb; unsigned idx;
        if (is_gt) { fb = __float_as_uint(__ldg(&hm[i])); idx = (unsigned)i; }
        else {
            unsigned long long key = g_cand[img][i];
            fb = ~(unsigned)(key >> 32);
            idx = (unsigned)(key & 0xFFFFFFFFULL);
        }
        if (val_bin(__uint_as_float(fb)) >= bstar) {
            int slot = atomicAdd(&s_nsurv, 1);
            if (slot < SURV)
                keys[slot] = ((unsigned long long)(~fb) << 32) | idx;
        }
    }
    __syncthreads();
    int ns = s_nsurv; if (ns > SURV) ns = SURV;
    if (tid >= ns) keys[tid] = 0xFFFFFFFFFFFFFFFFULL;
    __syncthreads();

    // bitonic sort ascending over 1024 keys (asc key == value desc, idx asc)
    for (unsigned kk = 2; kk <= SURV; kk <<= 1) {
        for (unsigned j = kk >> 1; j > 0; j >>= 1) {
            unsigned i = tid;
            unsigned ixj = i ^ j;
            if (ixj > i) {
                unsigned long long a = keys[i], b = keys[ixj];
                bool upd = ((i & kk) == 0);
                if ((a > b) == upd) { keys[i] = b; keys[ixj] = a; }
            }
            __syncthreads();
        }
    }

    if (tid < KTOP) {
        unsigned p = (unsigned)(keys[tid] & 0xFFFFFFFFULL);
        g_xs[img][tid] = (float)(p & (WID - 1));
        g_ys[img][tid] = (float)(p >> 8);
    }
    // reset consumed counter for the next graph replay
    if (!is_gt && tid == 0) g_cnt[img] = 0;
}

// ---------------------------------------------------------------------------
__device__ __forceinline__ void assemble(float* o, float xs, float ys,
                                         const float* wh, bool m) {
    // m is exactly 0/1 in the reference, so branching is bit-exact with blend
    o[0] = xs; o[1] = ys;
    if (m) {
        o[2] = xs + wh[0]; o[3] = ys + wh[1];
        o[4] = xs + wh[2]; o[5] = ys + wh[3];
        o[6] = xs + wh[4]; o[7] = ys + wh[5];
        o[8] = xs + wh[6]; o[9] = ys + wh[7];
    } else {
        o[2] = xs;                 o[3] = ys - wh[9] * 0.5f;
        o[4] = xs + wh[8] * 0.5f;  o[5] = ys;
        o[6] = xs;                 o[7] = ys + wh[9] * 0.5f;
        o[8] = xs - wh[8] * 0.5f;  o[9] = ys;
    }
}

#define LOSS_TPB 128
__global__ void k_loss(const float* __restrict__ pred_wh, const float* __restrict__ pred_reg,
                       const float* __restrict__ pred_cls,
                       const float* __restrict__ gt_wh, const float* __restrict__ gt_reg,
                       const float* __restrict__ gt_cls,
                       const int* __restrict__ gt_ind, const int* __restrict__ gt_mask,
                       float* __restrict__ out) {
    int t = blockIdx.x * LOSS_TPB + threadIdx.x;
    float lsum = 0.f;
    int lcnt = 0;
    if (t < NB * KTOP) {
        int b = t / KTOP;
        int k = t - b * KTOP;
        if (gt_mask[t] != 0) {
            lcnt = 10;
            int ind = gt_ind[t];
            float xs  = g_xs[b][k] + __ldg(&pred_reg[(size_t)(b * 2) * HW + ind]);
            float ys  = g_ys[b][k] + __ldg(&pred_reg[(size_t)(b * 2 + 1) * HW + ind]);
            float gxs = g_xs[NB + b][k] + __ldg(&gt_reg[2 * t]);
            float gys = g_ys[NB + b][k] + __ldg(&gt_reg[2 * t + 1]);
            float wh[10], gwh[10];
            #pragma unroll
            for (int c = 0; c < 10; c++)
                wh[c] = __ldg(&pred_wh[((size_t)b * 10 + c) * HW + ind]);
            #pragma unroll
            for (int c = 0; c < 10; c++)
                gwh[c] = __ldg(&gt_wh[10 * t + c]);
            bool m  = __ldg(&pred_cls[(size_t)b * HW + ind]) > 0.8f;
            bool gm = __ldg(&gt_cls[t]) > 0.8f;
            float pp[10], tt[10];
            assemble(pp, xs, ys, wh, m);
            assemble(tt, gxs, gys, gwh, gm);
            #pragma unroll
            for (int c = 0; c < 10; c++) {
                float d = fabsf(pp[c] - tt[c]);
                lsum += (d < 1.f) ? 0.5f * d * d : (d - 0.5f);
            }
        }
    }
    // block reduce
    #pragma unroll
    for (int off = 16; off > 0; off >>= 1) {
        lsum += __shfl_down_sync(0xffffffffu, lsum, off);
        lcnt += __shfl_down_sync(0xffffffffu, lcnt, off);
    }
    __shared__ float wsum[LOSS_TPB / 32];
    __shared__ int   wcnt[LOSS_TPB / 32];
    int warp = threadIdx.x >> 5, lane = threadIdx.x & 31;
    if (lane == 0) { wsum[warp] = lsum; wcnt[warp] = lcnt; }
    __syncthreads();
    if (threadIdx.x == 0) {
        float s = 0.f; int c = 0;
        #pragma unroll
        for (int w = 0; w < LOSS_TPB / 32; w++) { s += wsum[w]; c += wcnt[w]; }
        atomicAdd(&g_sum, (double)s);
        atomicAdd(&g_tot, c);
        __threadfence();
        unsigned ticket = atomicAdd(&g_ticket, 1u);
        if (ticket == gridDim.x - 1) {   // last block: finalize + reset state
            double fs = g_sum;
            int tot = g_tot;
            float loss = 0.f;
            if (tot > 0) loss = (float)(fs / (double)(tot < 1 ? 1 : tot));
            out[0] = loss;
            g_sum = 0.0; g_tot = 0; g_ticket = 0u;
        }
    }
}

// ---------------------------------------------------------------------------
extern "C" void kernel_launch(void* const* d_in, const int* in_sizes, int n_in,
                              void* d_out, int out_size) {
    const float* pred_hm  = (const float*)d_in[0];
    const float* pred_wh  = (const float*)d_in[1];
    const float* pred_reg = (const float*)d_in[2];
    const float* pred_cls = (const float*)d_in[3];
    const float* gt_hm    = (const float*)d_in[4];
    const float* gt_wh    = (const float*)d_in[5];
    const float* gt_reg   = (const float*)d_in[6];
    const float* gt_cls   = (const float*)d_in[7];
    const int*   gt_ind   = (const int*)d_in[8];
    const int*   gt_mask  = (const int*)d_in[9];
    float* out = (float*)d_out;

    k_nms<<<dim3(WID, NB), WID>>>(pred_hm);
    k_select<<<NIMG, 1024>>>(gt_hm);
    k_loss<<<(NB * KTOP + LOSS_TPB - 1) / LOSS_TPB, LOSS_TPB>>>(
        pred_wh, pred_reg, pred_cls, gt_wh, gt_reg, gt_cls, gt_ind, gt_mask, out);
}

// round 7
// speedup vs baseline: 1.2324x; 1.2282x over previous
#include <cuda_runtime.h>
#include <cuda_bf16.h>
#include <cstdint>

// Problem constants (B=32, C=1 heat, H=W=256, K=500)
#define NB     32
#define WID    256
#define HW     65536
#define KTOP   500
#define NIMG   64          // 32 pred images (NMS'd) + 32 gt images (raw)
#define CAND_MAX 8192      // max stored NMS candidates per pred image (~7.3k expected)
#define SURV   1024        // survivors after value-bin prune (E~516, 20-sigma margin)
#define BINS   4096        // value-based bins: bin = clamp((int)(v*4096), 0, 4095)

#define RCHUNK 32          // rows per k_nms block
#define NCHUNK (WID / RCHUNK)   // 8
#define STAGE_MAX 1280     // per-block candidate staging (E~925, ~+9 sigma)

// Scratch (static device globals — zero-initialized; every consumer resets what
// it consumed so graph replays see the same initial state)
__device__ unsigned long long g_cand[NB][CAND_MAX];   // 2 MB (pred only)
__device__ int      g_cnt[NB];
__device__ float    g_xs[NIMG][KTOP];
__device__ float    g_ys[NIMG][KTOP];
__device__ double   g_sum;
__device__ int      g_tot;
__device__ unsigned g_ticket;

__device__ __forceinline__ int val_bin(float v) {
    int b = (int)(v * 4096.0f);
    if (b < 0) b = 0;
    if (b > BINS - 1) b = BINS - 1;
    return b;   // monotone non-decreasing in v
}

__device__ __forceinline__ unsigned long long uomin(unsigned long long a, unsigned long long b) { return a < b ? a : b; }
__device__ __forceinline__ unsigned long long uomax(unsigned long long a, unsigned long long b) { return a > b ? a : b; }

// ---------------------------------------------------------------------------
// 3x3 NMS on PRED heatmaps only (reference NMS-es pred_hm, not gt_hm).
// One block per (image, 32-row chunk): stage 34 rows in smem once, then pure
// smem compute with a rolling horizontal-max window. A pixel survives iff
// v > 0 and v >= max of its 3x3 window (window includes v, so this is exactly
// hmax == heat). Candidates staged in smem; ONE global atomic per block.
__global__ void __launch_bounds__(WID) k_nms(const float* __restrict__ pred_hm) {
    __shared__ float rows[RCHUNK + 2][WID];              // 34.8 KB
    __shared__ unsigned long long stage[STAGE_MAX];      // 10 KB
    __shared__ int s_cnt, s_base;

    int img   = blockIdx.x >> 3;          // / NCHUNK
    int chunk = blockIdx.x & (NCHUNK - 1);
    int y0 = chunk * RCHUNK;
    const float* hm = pred_hm + (size_t)img * HW;
    int x = threadIdx.x;

    #pragma unroll
    for (int r = 0; r < RCHUNK + 2; r++) {
        int y = y0 - 1 + r;
        rows[r][x] = (y >= 0 && y < WID) ? __ldg(&hm[y * WID + x]) : -1.0f;
    }
    if (x == 0) s_cnt = 0;
    __syncthreads();

    // rolling horizontal max of 3 consecutive rows
    auto hmax3 = [&](int r) {
        float m = rows[r][x];
        if (x > 0)       m = fmaxf(m, rows[r][x - 1]);
        if (x < WID - 1) m = fmaxf(m, rows[r][x + 1]);
        return m;
    };
    float hprev = hmax3(0);
    float hcur  = hmax3(1);
    int lane = x & 31;

    #pragma unroll 4
    for (int r = 1; r <= RCHUNK; r++) {
        float hnext = hmax3(r + 1);
        float v = rows[r][x];
        bool ok = (v > 0.0f) && (v >= hprev) && (v >= hcur) && (v >= hnext);
        unsigned ballot = __ballot_sync(0xffffffffu, ok);
        if (ok) {
            int leader = __ffs(ballot) - 1;
            int base = 0;
            if (lane == leader) base = atomicAdd(&s_cnt, __popc(ballot));
            base = __shfl_sync(ballot, base, leader);
            int slot = base + __popc(ballot & ((1u << lane) - 1u));
            if (slot < STAGE_MAX) {
                unsigned fb = __float_as_uint(v);   // v > 0 => monotone bits
                stage[slot] = ((unsigned long long)(~fb) << 32)
                            | (unsigned)((y0 - 1 + r) * WID + x);
            }
        }
        hprev = hcur; hcur = hnext;
    }
    __syncthreads();

    int cnt = s_cnt; if (cnt > STAGE_MAX) cnt = STAGE_MAX;
    if (x == 0) s_base = atomicAdd(&g_cnt[img], cnt);
    __syncthreads();
    int base = s_base;
    for (int i = x; i < cnt; i += WID) {
        int slot = base + i;
        if (slot < CAND_MAX) g_cand[img][slot] = stage[i];
    }
}

// ---------------------------------------------------------------------------
// Per-image exact ordered top-500.
//   img <  NB : candidates = NMS survivors (g_cand)
//   img >= NB : candidates = ALL raw pixels of gt_hm (reference has no gt NMS)
// 1) 4096 value-bins histogram  2) warp suffix-scan -> bin of rank 500
// 3) collect survivors (E~516)  4) bitonic sort 1024 keys (shuffle stages for
//    j<=16, smem only for j>=32) -> ranks 0..499
__global__ void __launch_bounds__(1024) k_select(const float* __restrict__ gt_hm) {
    __shared__ int hist[BINS];                 // 16 KB
    __shared__ unsigned long long keys[SURV];  // 8 KB
    __shared__ int psum[1024];                 // 4 KB
    __shared__ int wsuf[32];
    __shared__ int s_bstar;
    __shared__ int s_nsurv;

    int img = blockIdx.x;
    int tid = threadIdx.x;
    int lane = tid & 31, warp = tid >> 5;
    bool is_gt = (img >= NB);
    const float* hm = is_gt ? (gt_hm + (size_t)(img - NB) * HW) : nullptr;
    int n;
    if (is_gt) n = HW;
    else { n = g_cnt[img]; if (n > CAND_MAX) n = CAND_MAX; }
    int n_pad = (n + 1023) & ~1023;

    for (int i = tid; i < BINS; i += 1024) hist[i] = 0;
    if (tid == 0) { s_bstar = 0; s_nsurv = 0; }
    __syncthreads();

    for (int i = tid; i < n_pad; i += 1024) {
        if (i < n) {
            float v = is_gt ? __ldg(&hm[i])
                            : __uint_as_float(~(unsigned)(g_cand[img][i] >> 32));
            atomicAdd(&hist[val_bin(v)], 1);
        }
    }
    __syncthreads();

    // group sums of 4 bins, then warp-level inclusive suffix scan over 1024
    int gv = hist[4*tid] + hist[4*tid+1] + hist[4*tid+2] + hist[4*tid+3];
    int v = gv;
    #pragma unroll
    for (int off = 1; off < 32; off <<= 1) {
        int t2 = __shfl_down_sync(0xffffffffu, v, off);
        if (lane + off < 32) v += t2;
    }
    if (lane == 0) wsuf[warp] = v;   // warp total = suffix at lane 0
    __syncthreads();
    if (warp == 0) {
        int t = wsuf[lane];
        #pragma unroll
        for (int off = 1; off < 32; off <<= 1) {
            int t2 = __shfl_down_sync(0xffffffffu, t, off);
            if (lane + off < 32) t += t2;
        }
        wsuf[lane] = t;              // inclusive suffix of warp totals
    }
    __syncthreads();
    int suffix = v + ((warp < 31) ? wsuf[warp + 1] : 0);  // inclusive suffix over groups
    psum[tid] = suffix;
    __syncthreads();

    // unique boundary group: suffix(t) >= K but suffix(t+1) < K
    int above = (tid < 1023) ? psum[tid + 1] : 0;
    if (psum[tid] >= KTOP && above < KTOP) {
        int c = above;
        int bstar = 4 * tid;
        for (int b = 4 * tid + 3; b >= 4 * tid; --b) {
            c += hist[b];
            if (c >= KTOP) { bstar = b; break; }
        }
        s_bstar = bstar;
    }
    __syncthreads();

    int bstar = s_bstar;
    for (int i = tid; i < n_pad; i += 1024) {
        unsigned fb = 0; unsigned idx = 0;
        bool pass = false;
        if (i < n) {
            if (is_gt) { fb = __float_as_uint(__ldg(&hm[i])); idx = (unsigned)i; }
            else {
                unsigned long long key = g_cand[img][i];
                fb = ~(unsigned)(key >> 32);
                idx = (unsigned)(key & 0xFFFFFFFFULL);
            }
            pass = (val_bin(__uint_as_float(fb)) >= bstar);
        }
        unsigned ballot = __ballot_sync(0xffffffffu, pass);
        if (pass) {
            int leader = __ffs(ballot) - 1;
            int base = 0;
            if (lane == leader) base = atomicAdd(&s_nsurv, __popc(ballot));
            base = __shfl_sync(ballot, base, leader);
            int slot = base + __popc(ballot & ((1u << lane) - 1u));
            if (slot < SURV)
                keys[slot] = ((unsigned long long)(~fb) << 32) | idx;
        }
    }
    __syncthreads();
    int ns = s_nsurv; if (ns > SURV) ns = SURV;
    if (tid >= ns) keys[tid] = 0xFFFFFFFFFFFFFFFFULL;
    __syncthreads();

    // ---- bitonic sort ascending over 1024 keys ----
    // asc 64-bit key == (value desc, idx asc) == lax.top_k order.
    // kk = 2..32: all stages intra-warp -> pure register/shuffle, no barriers.
    {
        unsigned long long kv = keys[tid];
        #pragma unroll
        for (unsigned kk = 2; kk <= 32; kk <<= 1) {
            bool up = ((tid & kk) == 0);
            #pragma unroll
            for (unsigned j = kk >> 1; j >= 1; j >>= 1) {
                unsigned long long pv = __shfl_xor_sync(0xffffffffu, kv, j);
                bool keepmin = (((tid & j) == 0) == up);
                kv = keepmin ? uomin(kv, pv) : uomax(kv, pv);
            }
        }
        keys[tid] = kv;
    }
    __syncthreads();
    // kk = 64..1024: stages j>=32 via smem, j<=16 via shuffles
    for (unsigned kk = 64; kk <= SURV; kk <<= 1) {
        bool up = ((tid & kk) == 0);
        for (unsigned j = kk >> 1; j >= 32; j >>= 1) {
            unsigned ixj = tid ^ j;
            if (ixj > tid) {
                unsigned long long a = keys[tid], b = keys[ixj];
                if ((a > b) == up) { keys[tid] = b; keys[ixj] = a; }
            }
            __syncthreads();
        }
        unsigned long long kv = keys[tid];
        #pragma unroll
        for (unsigned j = 16; j >= 1; j >>= 1) {
            unsigned long long pv = __shfl_xor_sync(0xffffffffu, kv, j);
            bool keepmin = (((tid & j) == 0) == up);
            kv = keepmin ? uomin(kv, pv) : uomax(kv, pv);
        }
        keys[tid] = kv;
        __syncthreads();
    }

    if (tid < KTOP) {
        unsigned p = (unsigned)(keys[tid] & 0xFFFFFFFFULL);
        g_xs[img][tid] = (float)(p & (WID - 1));
        g_ys[img][tid] = (float)(p >> 8);
    }
    // reset consumed counter for the next graph replay
    if (!is_gt && tid == 0) g_cnt[img] = 0;
}

// ---------------------------------------------------------------------------
__device__ __forceinline__ void assemble(float* o, float xs, float ys,
                                         const float* wh, bool m) {
    // m is exactly 0/1 in the reference, so branching is bit-exact with blend
    o[0] = xs; o[1] = ys;
    if (m) {
        o[2] = xs + wh[0]; o[3] = ys + wh[1];
        o[4] = xs + wh[2]; o[5] = ys + wh[3];
        o[6] = xs + wh[4]; o[7] = ys + wh[5];
        o[8] = xs + wh[6]; o[9] = ys + wh[7];
    } else {
        o[2] = xs;                 o[3] = ys - wh[9] * 0.5f;
        o[4] = xs + wh[8] * 0.5f;  o[5] = ys;
        o[6] = xs;                 o[7] = ys + wh[9] * 0.5f;
        o[8] = xs - wh[8] * 0.5f;  o[9] = ys;
    }
}

#define LOSS_TPB 128
__global__ void k_loss(const float* __restrict__ pred_wh, const float* __restrict__ pred_reg,
                       const float* __restrict__ pred_cls,
                       const float* __restrict__ gt_wh, const float* __restrict__ gt_reg,
                       const float* __restrict__ gt_cls,
                       const int* __restrict__ gt_ind, const int* __restrict__ gt_mask,
                       float* __restrict__ out) {
    int t = blockIdx.x * LOSS_TPB + threadIdx.x;
    float lsum = 0.f;
    int lcnt = 0;
    if (t < NB * KTOP) {
        int b = t / KTOP;
        int k = t - b * KTOP;
        if (gt_mask[t] != 0) {
            lcnt = 10;
            int ind = gt_ind[t];
            float xs  = g_xs[b][k] + __ldg(&pred_reg[(size_t)(b * 2) * HW + ind]);
            float ys  = g_ys[b][k] + __ldg(&pred_reg[(size_t)(b * 2 + 1) * HW + ind]);
            float gxs = g_xs[NB + b][k] + __ldg(&gt_reg[2 * t]);
            float gys = g_ys[NB + b][k] + __ldg(&gt_reg[2 * t + 1]);
            float wh[10], gwh[10];
            #pragma unroll
            for (int c = 0; c < 10; c++)
                wh[c] = __ldg(&pred_wh[((size_t)b * 10 + c) * HW + ind]);
            #pragma unroll
            for (int c = 0; c < 10; c++)
                gwh[c] = __ldg(&gt_wh[10 * t + c]);
            bool m  = __ldg(&pred_cls[(size_t)b * HW + ind]) > 0.8f;
            bool gm = __ldg(&gt_cls[t]) > 0.8f;
            float pp[10], tt[10];
            assemble(pp, xs, ys, wh, m);
            assemble(tt, gxs, gys, gwh, gm);
            #pragma unroll
            for (int c = 0; c < 10; c++) {
                float d = fabsf(pp[c] - tt[c]);
                lsum += (d < 1.f) ? 0.5f * d * d : (d - 0.5f);
            }
        }
    }
    // block reduce
    #pragma unroll
    for (int off = 16; off > 0; off >>= 1) {
        lsum += __shfl_down_sync(0xffffffffu, lsum, off);
        lcnt += __shfl_down_sync(0xffffffffu, lcnt, off);
    }
    __shared__ float wsum[LOSS_TPB / 32];
    __shared__ int   wcnt[LOSS_TPB / 32];
    int warp = threadIdx.x >> 5, lane = threadIdx.x & 31;
    if (lane == 0) { wsum[warp] = lsum; wcnt[warp] = lcnt; }
    __syncthreads();
    if (threadIdx.x == 0) {
        float s = 0.f; int c = 0;
        #pragma unroll
        for (int w = 0; w < LOSS_TPB / 32; w++) { s += wsum[w]; c += wcnt[w]; }
        atomicAdd(&g_sum, (double)s);
        atomicAdd(&g_tot, c);
        __threadfence();
        unsigned ticket = atomicAdd(&g_ticket, 1u);
        if (ticket == gridDim.x - 1) {   // last block: finalize + reset state
            double fs = g_sum;
            int tot = g_tot;
            float loss = 0.f;
            if (tot > 0) loss = (float)(fs / (double)(tot < 1 ? 1 : tot));
            out[0] = loss;
            g_sum = 0.0; g_tot = 0; g_ticket = 0u;
        }
    }
}

// ---------------------------------------------------------------------------
extern "C" void kernel_launch(void* const* d_in, const int* in_sizes, int n_in,
                              void* d_out, int out_size) {
    const float* pred_hm  = (const float*)d_in[0];
    const float* pred_wh  = (const float*)d_in[1];
    const float* pred_reg = (const float*)d_in[2];
    const float* pred_cls = (const float*)d_in[3];
    const float* gt_hm    = (const float*)d_in[4];
    const float* gt_wh    = (const float*)d_in[5];
    const float* gt_reg   = (const float*)d_in[6];
    const float* gt_cls   = (const float*)d_in[7];
    const int*   gt_ind   = (const int*)d_in[8];
    const int*   gt_mask  = (const int*)d_in[9];
    float* out = (float*)d_out;

    k_nms<<<NB * NCHUNK, WID>>>(pred_hm);
    k_select<<<NIMG, 1024>>>(gt_hm);
    k_loss<<<(NB * KTOP + LOSS_TPB - 1) / LOSS_TPB, LOSS_TPB>>>(
        pred_wh, pred_reg, pred_cls, gt_wh, gt_reg, gt_cls, gt_ind, gt_mask, out);
}

// round 8
// speedup vs baseline: 2.1183x; 1.7188x over previous
#include <cuda_runtime.h>
#include <cuda_bf16.h>
#include <cstdint>

// Problem constants (B=32, C=1 heat, H=W=256, K=500)
#define NB     32
#define WID    256
#define HW     65536
#define KTOP   500
#define NIMG   64          // 32 pred images (NMS'd) + 32 gt images (raw)
#define CAND_MAX 8192      // max stored NMS candidates per pred image (~7.3k expected)
#define SURV   1024        // survivors after value-bin prune (E~516, 20-sigma margin)
#define BINS   4096        // value-based bins: bin = clamp((int)(v*4096), 0, 4095)

#define RCHUNK 8                 // rows per k_nms block
#define NCHUNK (WID / RCHUNK)    // 32
#define STAGE_MAX 512            // per-block candidate staging (E~228, +20 sigma)

// Scratch (static device globals — zero-initialized; every consumer resets what
// it consumed so graph replays see the same initial state)
__device__ unsigned long long g_cand[NB][CAND_MAX];   // 2 MB (pred only)
__device__ int      g_cnt[NB];
__device__ float    g_xs[NIMG][KTOP];
__device__ float    g_ys[NIMG][KTOP];
__device__ double   g_sum;
__device__ int      g_tot;
__device__ unsigned g_ticket;

// per-coordinate assembly tables (see reference _assemble)
__constant__ int   c_whA[10] = {-1,-1, 0, 1, 2, 3, 4, 5, 6, 7};   // m==1: wh channel
__constant__ int   c_whB[10] = {-1,-1,-1, 9, 8,-1,-1, 9, 8,-1};   // m==0: wh channel
__constant__ float c_sgn[10] = {0,0,0,-0.5f,0.5f,0,0,0.5f,-0.5f,0};

__device__ __forceinline__ int val_bin(float v) {
    int b = (int)(v * 4096.0f);
    if (b < 0) b = 0;
    if (b > BINS - 1) b = BINS - 1;
    return b;   // monotone non-decreasing in v
}

__device__ __forceinline__ unsigned long long uomin(unsigned long long a, unsigned long long b) { return a < b ? a : b; }
__device__ __forceinline__ unsigned long long uomax(unsigned long long a, unsigned long long b) { return a > b ? a : b; }

// ---------------------------------------------------------------------------
// 3x3 NMS on PRED heatmaps only (reference NMS-es pred_hm, not gt_hm).
// One block per (image, 8-row chunk): 10 rows staged in smem, rolling 3-row
// horizontal max. Pixel survives iff v>0 and v >= max of 3x3 window
// (window includes v => exactly hmax==heat). One global atomic per block.
__global__ void __launch_bounds__(WID) k_nms(const float* __restrict__ pred_hm) {
    __shared__ float rows[RCHUNK + 2][WID];              // 10 KB
    __shared__ unsigned long long stage[STAGE_MAX];      // 4 KB
    __shared__ int s_cnt, s_base;

    int img   = blockIdx.x >> 5;            // / NCHUNK
    int chunk = blockIdx.x & (NCHUNK - 1);
    int y0 = chunk * RCHUNK;
    const float* hm = pred_hm + (size_t)img * HW;
    int x = threadIdx.x;

    #pragma unroll
    for (int r = 0; r < RCHUNK + 2; r++) {
        int y = y0 - 1 + r;
        rows[r][x] = (y >= 0 && y < WID) ? __ldg(&hm[y * WID + x]) : -1.0f;
    }
    if (x == 0) s_cnt = 0;
    __syncthreads();

    auto hmax3 = [&](int r) {
        float m = rows[r][x];
        if (x > 0)       m = fmaxf(m, rows[r][x - 1]);
        if (x < WID - 1) m = fmaxf(m, rows[r][x + 1]);
        return m;
    };
    float hprev = hmax3(0);
    float hcur  = hmax3(1);
    int lane = x & 31;

    #pragma unroll
    for (int r = 1; r <= RCHUNK; r++) {
        float hnext = hmax3(r + 1);
        float v = rows[r][x];
        bool ok = (v > 0.0f) && (v >= hprev) && (v >= hcur) && (v >= hnext);
        unsigned ballot = __ballot_sync(0xffffffffu, ok);
        if (ok) {
            int leader = __ffs(ballot) - 1;
            int base = 0;
            if (lane == leader) base = atomicAdd(&s_cnt, __popc(ballot));
            base = __shfl_sync(ballot, base, leader);
            int slot = base + __popc(ballot & ((1u << lane) - 1u));
            if (slot < STAGE_MAX) {
                unsigned fb = __float_as_uint(v);   // v > 0 => monotone bits
                stage[slot] = ((unsigned long long)(~fb) << 32)
                            | (unsigned)((y0 - 1 + r) * WID + x);
            }
        }
        hprev = hcur; hcur = hnext;
    }
    __syncthreads();

    int cnt = s_cnt; if (cnt > STAGE_MAX) cnt = STAGE_MAX;
    if (x == 0) s_base = atomicAdd(&g_cnt[img], cnt);
    __syncthreads();
    int base = s_base;
    for (int i = x; i < cnt; i += WID) {
        int slot = base + i;
        if (slot < CAND_MAX) g_cand[img][slot] = stage[i];
    }
}

// ---------------------------------------------------------------------------
// Per-image exact ordered top-500 (one CTA per image).
//   IS_GT=false: candidates = NMS survivors (g_cand), output rows [0, NB)
//   IS_GT=true : candidates = ALL raw pixels of gt_hm (no NMS in reference!),
//                output rows [NB, 2NB), float4-vectorized streaming.
// 1) 4096 value-bin histogram  2) warp suffix-scan -> bin holding rank 500
// 3) warp-aggregated survivor collection (E~516)  4) bitonic 1024 sort of
//    (~fbits<<32)|idx  == lax.top_k order (value desc, idx asc).
template <bool IS_GT>
__global__ void __launch_bounds__(1024) k_select(const float* __restrict__ gt_hm) {
    __shared__ int hist[BINS];                 // 16 KB
    __shared__ unsigned long long keys[SURV];  // 8 KB
    __shared__ int psum[1024];                 // 4 KB
    __shared__ int wsuf[32];
    __shared__ int s_bstar;
    __shared__ int s_nsurv;

    int blk = blockIdx.x;                      // 0..NB-1
    int img = IS_GT ? (NB + blk) : blk;        // output row
    int tid = threadIdx.x;
    int lane = tid & 31, warp = tid >> 5;
    const float4* hm4 = IS_GT
        ? reinterpret_cast<const float4*>(gt_hm + (size_t)blk * HW) : nullptr;

    int n = 0;
    if (!IS_GT) { n = g_cnt[blk]; if (n > CAND_MAX) n = CAND_MAX; }

    for (int i = tid; i < BINS; i += 1024) hist[i] = 0;
    if (tid == 0) { s_bstar = 0; s_nsurv = 0; }
    __syncthreads();

    // ---- histogram ----
    if (IS_GT) {
        #pragma unroll 4
        for (int i = tid; i < HW / 4; i += 1024) {
            float4 v = __ldg(&hm4[i]);
            atomicAdd(&hist[val_bin(v.x)], 1);
            atomicAdd(&hist[val_bin(v.y)], 1);
            atomicAdd(&hist[val_bin(v.z)], 1);
            atomicAdd(&hist[val_bin(v.w)], 1);
        }
    } else {
        for (int i = tid; i < n; i += 1024) {
            float v = __uint_as_float(~(unsigned)(g_cand[blk][i] >> 32));
            atomicAdd(&hist[val_bin(v)], 1);
        }
    }
    __syncthreads();

    // ---- suffix scan over 1024 groups of 4 bins ----
    int gv = hist[4*tid] + hist[4*tid+1] + hist[4*tid+2] + hist[4*tid+3];
    int v = gv;
    #pragma unroll
    for (int off = 1; off < 32; off <<= 1) {
        int t2 = __shfl_down_sync(0xffffffffu, v, off);
        if (lane + off < 32) v += t2;
    }
    if (lane == 0) wsuf[warp] = v;
    __syncthreads();
    if (warp == 0) {
        int t = wsuf[lane];
        #pragma unroll
        for (int off = 1; off < 32; off <<= 1) {
            int t2 = __shfl_down_sync(0xffffffffu, t, off);
            if (lane + off < 32) t += t2;
        }
        wsuf[lane] = t;
    }
    __syncthreads();
    int suffix = v + ((warp < 31) ? wsuf[warp + 1] : 0);
    psum[tid] = suffix;
    __syncthreads();

    int above = (tid < 1023) ? psum[tid + 1] : 0;
    if (psum[tid] >= KTOP && above < KTOP) {
        int c = above;
        int bstar = 4 * tid;
        for (int b = 4 * tid + 3; b >= 4 * tid; --b) {
            c += hist[b];
            if (c >= KTOP) { bstar = b; break; }
        }
        s_bstar = bstar;
    }
    __syncthreads();
    int bstar = s_bstar;

    // ---- collect survivors (warp-aggregated append) ----
    if (IS_GT) {
        #pragma unroll 4
        for (int i = tid; i < HW / 4; i += 1024) {
            float4 v4 = __ldg(&hm4[i]);
            float vv[4] = {v4.x, v4.y, v4.z, v4.w};
            #pragma unroll
            for (int comp = 0; comp < 4; comp++) {
                bool pass = (val_bin(vv[comp]) >= bstar);
                unsigned ballot = __ballot_sync(0xffffffffu, pass);
                if (pass) {
                    int leader = __ffs(ballot) - 1;
                    int base = 0;
                    if (lane == leader) base = atomicAdd(&s_nsurv, __popc(ballot));
                    base = __shfl_sync(ballot, base, leader);
                    int slot = base + __popc(ballot & ((1u << lane) - 1u));
                    if (slot < SURV) {
                        unsigned fb = __float_as_uint(vv[comp]);
                        keys[slot] = ((unsigned long long)(~fb) << 32)
                                   | (unsigned)(4 * i + comp);
                    }
                }
            }
        }
    } else {
        int n_pad = (n + 1023) & ~1023;
        for (int i = tid; i < n_pad; i += 1024) {
            unsigned long long key = 0; bool pass = false;
            if (i < n) {
                key = g_cand[blk][i];
                float vv = __uint_as_float(~(unsigned)(key >> 32));
                pass = (val_bin(vv) >= bstar);
            }
            unsigned ballot = __ballot_sync(0xffffffffu, pass);
            if (pass) {
                int leader = __ffs(ballot) - 1;
                int base = 0;
                if (lane == leader) base = atomicAdd(&s_nsurv, __popc(ballot));
                base = __shfl_sync(ballot, base, leader);
                int slot = base + __popc(ballot & ((1u << lane) - 1u));
                if (slot < SURV) keys[slot] = key;
            }
        }
    }
    __syncthreads();
    int ns = s_nsurv; if (ns > SURV) ns = SURV;
    if (tid >= ns) keys[tid] = 0xFFFFFFFFFFFFFFFFULL;
    __syncthreads();

    // ---- bitonic sort ascending over 1024 keys ----
    {
        unsigned long long kv = keys[tid];
        #pragma unroll
        for (unsigned kk = 2; kk <= 32; kk <<= 1) {
            bool up = ((tid & kk) == 0);
            #pragma unroll
            for (unsigned j = kk >> 1; j >= 1; j >>= 1) {
                unsigned long long pv = __shfl_xor_sync(0xffffffffu, kv, j);
                bool keepmin = (((tid & j) == 0) == up);
                kv = keepmin ? uomin(kv, pv) : uomax(kv, pv);
            }
        }
        keys[tid] = kv;
    }
    __syncthreads();
    for (unsigned kk = 64; kk <= SURV; kk <<= 1) {
        bool up = ((tid & kk) == 0);
        for (unsigned j = kk >> 1; j >= 32; j >>= 1) {
            unsigned ixj = tid ^ j;
            if (ixj > tid) {
                unsigned long long a = keys[tid], b = keys[ixj];
                if ((a > b) == up) { keys[tid] = b; keys[ixj] = a; }
            }
            __syncthreads();
        }
        unsigned long long kv = keys[tid];
        #pragma unroll
        for (unsigned j = 16; j >= 1; j >>= 1) {
            unsigned long long pv = __shfl_xor_sync(0xffffffffu, kv, j);
            bool keepmin = (((tid & j) == 0) == up);
            kv = keepmin ? uomin(kv, pv) : uomax(kv, pv);
        }
        keys[tid] = kv;
        __syncthreads();
    }

    if (tid < KTOP) {
        unsigned p = (unsigned)(keys[tid] & 0xFFFFFFFFULL);
        g_xs[img][tid] = (float)(p & (WID - 1));
        g_ys[img][tid] = (float)(p >> 8);
    }
    if (!IS_GT && tid == 0) g_cnt[blk] = 0;   // reset for next graph replay
}

// ---------------------------------------------------------------------------
// Loss: one thread per (item, coordinate) — 160K threads, ~6 loads each.
#define LOSS_TPB 1024
#define LOSS_N   (NB * KTOP * 10)
__global__ void __launch_bounds__(LOSS_TPB)
k_loss(const float* __restrict__ pred_wh, const float* __restrict__ pred_reg,
       const float* __restrict__ pred_cls,
       const float* __restrict__ gt_wh, const float* __restrict__ gt_reg,
       const float* __restrict__ gt_cls,
       const int* __restrict__ gt_ind, const int* __restrict__ gt_mask,
       float* __restrict__ out) {
    int gidx = blockIdx.x * LOSS_TPB + threadIdx.x;
    float lsum = 0.f;
    int lcnt = 0;
    if (gidx < LOSS_N) {
        int t = gidx / 10;
        int c = gidx - t * 10;
        if (gt_mask[t] != 0) {
            lcnt = 1;
            int b = t / KTOP;
            int k = t - b * KTOP;
            int ind = gt_ind[t];
            bool odd = (c & 1);
            // base coordinate (xs or ys), including the reg offset
            float base, gbase;
            if (odd) {
                base  = g_xs[0][0];  // dummy init (avoid compiler warning path)
                base  = g_ys[b][k]      + __ldg(&pred_reg[(size_t)(b * 2 + 1) * HW + ind]);
                gbase = g_ys[NB + b][k] + __ldg(&gt_reg[2 * t + 1]);
            } else {
                base  = g_xs[b][k]      + __ldg(&pred_reg[(size_t)(b * 2) * HW + ind]);
                gbase = g_xs[NB + b][k] + __ldg(&gt_reg[2 * t]);
            }
            bool m  = __ldg(&pred_cls[(size_t)b * HW + ind]) > 0.8f;
            bool gm = __ldg(&gt_cls[t]) > 0.8f;
            int iA = c_whA[c], iB = c_whB[c];
            float sg = c_sgn[c];
            float pp = base, tt = gbase;
            if (m) {
                if (iA >= 0) pp += __ldg(&pred_wh[((size_t)b * 10 + iA) * HW + ind]);
            } else {
                if (iB >= 0) pp += sg * __ldg(&pred_wh[((size_t)b * 10 + iB) * HW + ind]);
            }
            if (gm) {
                if (iA >= 0) tt += __ldg(&gt_wh[10 * t + iA]);
            } else {
                if (iB >= 0) tt += sg * __ldg(&gt_wh[10 * t + iB]);
            }
            float d = fabsf(pp - tt);
            lsum = (d < 1.f) ? 0.5f * d * d : (d - 0.5f);
        }
    }
    // block reduce (32 warps)
    #pragma unroll
    for (int off = 16; off > 0; off >>= 1) {
        lsum += __shfl_down_sync(0xffffffffu, lsum, off);
        lcnt += __shfl_down_sync(0xffffffffu, lcnt, off);
    }
    __shared__ float wsum[LOSS_TPB / 32];
    __shared__ int   wcnt[LOSS_TPB / 32];
    int warp = threadIdx.x >> 5, lane = threadIdx.x & 31;
    if (lane == 0) { wsum[warp] = lsum; wcnt[warp] = lcnt; }
    __syncthreads();
    if (warp == 0) {
        float s = (lane < LOSS_TPB / 32) ? wsum[lane] : 0.f;
        int   cc = (lane < LOSS_TPB / 32) ? wcnt[lane] : 0;
        #pragma unroll
        for (int off = 16; off > 0; off >>= 1) {
            s  += __shfl_down_sync(0xffffffffu, s, off);
            cc += __shfl_down_sync(0xffffffffu, cc, off);
        }
        if (lane == 0) {
            atomicAdd(&g_sum, (double)s);
            atomicAdd(&g_tot, cc);
            __threadfence();
            unsigned ticket = atomicAdd(&g_ticket, 1u);
            if (ticket == gridDim.x - 1) {   // last block: finalize + reset
                double fs = g_sum;
                int tot = g_tot;
                float loss = 0.f;
                if (tot > 0) loss = (float)(fs / (double)(tot < 1 ? 1 : tot));
                out[0] = loss;
                g_sum = 0.0; g_tot = 0; g_ticket = 0u;
            }
        }
    }
}

// ---------------------------------------------------------------------------
extern "C" void kernel_launch(void* const* d_in, const int* in_sizes, int n_in,
                              void* d_out, int out_size) {
    const float* pred_hm  = (const float*)d_in[0];
    const float* pred_wh  = (const float*)d_in[1];
    const float* pred_reg = (const float*)d_in[2];
    const float* pred_cls = (const float*)d_in[3];
    const float* gt_hm    = (const float*)d_in[4];
    const float* gt_wh    = (const float*)d_in[5];
    const float* gt_reg   = (const float*)d_in[6];
    const float* gt_cls   = (const float*)d_in[7];
    const int*   gt_ind   = (const int*)d_in[8];
    const int*   gt_mask  = (const int*)d_in[9];
    float* out = (float*)d_out;

    // side stream for the gt top-k branch (independent of pred NMS path).
    // Created once on the first (non-captured) correctness call; fork/join via
    // events so graph capture records two parallel branches.
    static cudaStream_t s2 = nullptr;
    static cudaEvent_t evFork = nullptr, evJoin = nullptr;
    if (s2 == nullptr) {
        cudaStreamCreateWithFlags(&s2, cudaStreamNonBlocking);
        cudaEventCreateWithFlags(&evFork, cudaEventDisableTiming);
        cudaEventCreateWithFlags(&evJoin, cudaEventDisableTiming);
    }

    cudaEventRecord(evFork, 0);
    cudaStreamWaitEvent(s2, evFork, 0);
    k_select<true><<<NB, 1024, 0, s2>>>(gt_hm);           // gt branch
    cudaEventRecord(evJoin, s2);

    k_nms<<<NB * NCHUNK, WID>>>(pred_hm);                 // pred branch
    k_select<false><<<NB, 1024>>>(gt_hm);

    cudaStreamWaitEvent(0, evJoin, 0);
    k_loss<<<(LOSS_N + LOSS_TPB - 1) / LOSS_TPB, LOSS_TPB>>>(
        pred_wh, pred_reg, pred_cls, gt_wh, gt_reg, gt_cls, gt_ind, gt_mask, out);
}